// round 6
// baseline (speedup 1.0000x reference)
#include <cuda_runtime.h>
#include <math.h>

#define BB 32
#define CC 256
#define CR 64
#define HW 16384            // 128*128
#define NROWS (BB * CC)     // 8192 worker blocks
#define NMLP  BB            // 32 epilogue blocks

// allocation-free scratch
__device__ float g_f0[BB * CC];
__device__ int   g_counter;   // rows completed (zero-init; reset each call)
__device__ int   g_done;      // MLP blocks completed

// ---------------------------------------------------------------------------
// Single fused kernel.
//   blocks [NMLP, NMLP+NROWS): row_mean of one (b,c) row -> g_f0, count up.
//   blocks [0, NMLP): prefetch weights into L2, spin for counter, then run
//                     the whole SE-MLP for batch b. Block 0 resets counters.
// ---------------------------------------------------------------------------
__global__ __launch_bounds__(256) void fused_se_kernel(const float* __restrict__ x,
                                                       const float* __restrict__ W1,
                                                       const float* __restrict__ W2,
                                                       const float* __restrict__ W3,
                                                       const float* __restrict__ b3,
                                                       float* __restrict__ out) {
    const int t = threadIdx.x;

    // ======================== worker path: row mean ========================
    if (blockIdx.x >= NMLP) {
        const int row = blockIdx.x - NMLP;               // b*C + c
        const float4* __restrict__ p =
            reinterpret_cast<const float4*>(x) + (size_t)row * (HW / 4);

        float s = 0.0f;
#pragma unroll
        for (int k = 0; k < 16; k++) {
            float4 v = __ldcs(p + k * 256 + t);
            s += (v.x + v.y) + (v.z + v.w);
        }
#pragma unroll
        for (int o = 16; o > 0; o >>= 1)
            s += __shfl_xor_sync(0xffffffffu, s, o);

        __shared__ float part[8];
        if ((t & 31) == 0) part[t >> 5] = s;
        __syncthreads();

        if (t < 8) {
            float v = part[t];
#pragma unroll
            for (int o = 4; o > 0; o >>= 1)
                v += __shfl_xor_sync(0x000000ffu, v, o);
            if (t == 0) {
                g_f0[row] = v * (1.0f / HW);
                __threadfence();
                atomicAdd(&g_counter, 1);
            }
        }
        return;
    }

    // ========================= epilogue path: MLP ==========================
    const int b    = blockIdx.x;
    const int warp = t >> 5;
    const int lane = t & 31;

    __shared__ float f0s[CC];
    __shared__ float hs[CR];
    __shared__ float ps[CC];

    // warm L2 with the weights while row_mean is still streaming
    {
        float dummy = 0.0f;
        for (int i = t; i < CR * CC; i += 256) dummy += __ldg(W1 + i);
        for (int i = t; i < CC * CR; i += 256) dummy += __ldg(W2 + i);
        for (int i = t; i < 2 * CC;  i += 256) dummy += __ldg(W3 + i);
        if (dummy == 1.0e38f) hs[0] = dummy;   // never taken; defeats DCE
    }

    // wait for all rows
    if (t == 0) {
        while (atomicAdd(&g_counter, 0) < NROWS) __nanosleep(128);
    }
    __syncthreads();
    __threadfence();

    if (t < CC) f0s[t] = g_f0[b * CC + t];
    __syncthreads();

    // ---- stage 1: h[j] = relu(f0 . W1[j,:]), 8 outputs/warp with ILP ------
    {
        float acc[8];
#pragma unroll
        for (int u = 0; u < 8; u++) acc[u] = 0.0f;
#pragma unroll
        for (int k = 0; k < 8; k++) {
            const int c = k * 32 + lane;
            const float f = f0s[c];
#pragma unroll
            for (int u = 0; u < 8; u++)
                acc[u] = fmaf(f, W1[(warp * 8 + u) * CC + c], acc[u]);
        }
#pragma unroll
        for (int o = 16; o > 0; o >>= 1)
#pragma unroll
            for (int u = 0; u < 8; u++)
                acc[u] += __shfl_xor_sync(0xffffffffu, acc[u], o);
        if (lane == 0) {
#pragma unroll
            for (int u = 0; u < 8; u++)
                hs[warp * 8 + u] = fmaxf(acc[u], 0.0f);
        }
    }
    __syncthreads();

    // ---- stage 2: p[c] = sigmoid(h . W2[c,:]) * f0[c], 32 outputs/warp ----
    {
        const float hv0 = hs[lane];
        const float hv1 = hs[lane + 32];
#pragma unroll
        for (int g = 0; g < 4; g++) {
            float acc[8];
#pragma unroll
            for (int u = 0; u < 8; u++) {
                const int c = warp * 32 + g * 8 + u;
                const float* __restrict__ w = W2 + c * CR;
                acc[u] = fmaf(hv0, w[lane], hv1 * w[lane + 32]);
            }
#pragma unroll
            for (int o = 16; o > 0; o >>= 1)
#pragma unroll
                for (int u = 0; u < 8; u++)
                    acc[u] += __shfl_xor_sync(0xffffffffu, acc[u], o);
            if (lane == 0) {
#pragma unroll
                for (int u = 0; u < 8; u++) {
                    const int c = warp * 32 + g * 8 + u;
                    const float gsig = 1.0f / (1.0f + __expf(-acc[u]));
                    ps[c] = gsig * f0s[c];
                }
            }
        }
    }
    __syncthreads();

    // ---- stage 3: out[b,o] = p . W3[o,:] + b3[o] --------------------------
    if (warp < 2) {
        const int o = warp;
        const float* __restrict__ w = W3 + o * CC;
        float acc = 0.0f;
#pragma unroll
        for (int k = 0; k < 8; k++) {
            const int c = k * 32 + lane;
            acc = fmaf(ps[c], w[c], acc);
        }
#pragma unroll
        for (int s = 16; s > 0; s >>= 1)
            acc += __shfl_xor_sync(0xffffffffu, acc, s);
        if (lane == 0) out[b * 2 + o] = acc + b3[o];
    }
    __syncthreads();

    // completion handshake + deterministic reset for graph replay
    if (t == 0) {
        __threadfence();
        atomicAdd(&g_done, 1);
        if (b == 0) {
            while (atomicAdd(&g_done, 0) < NMLP) __nanosleep(64);
            g_counter = 0;
            g_done    = 0;
            __threadfence();
        }
    }
}

// ---------------------------------------------------------------------------
extern "C" void kernel_launch(void* const* d_in, const int* in_sizes, int n_in,
                              void* d_out, int out_size) {
    const float* x  = (const float*)d_in[0];  // (32,256,128,128)
    const float* W1 = (const float*)d_in[1];  // (64,256)
    const float* W2 = (const float*)d_in[2];  // (256,64)
    const float* W3 = (const float*)d_in[3];  // (2,256)
    const float* b3 = (const float*)d_in[4];  // (2,)
    float* out = (float*)d_out;               // (32,2)

    fused_se_kernel<<<NMLP + NROWS, 256>>>(x, W1, W2, W3, b3, out);
}

// round 7
// speedup vs baseline: 1.0690x; 1.0690x over previous
#include <cuda_runtime.h>
#include <math.h>

#define BB 32
#define CC 256
#define CR 64
#define HW 16384   // 128*128

// allocation-free scratch: pooled means
__device__ float g_f0[BB * CC];

// dynamic smem layout (floats):
//   W1s [CR*CC] | W2s [CC*CR] | W3s [2*CC] | f0s [CC] | hs [CR] | ps [CC]
#define SMEM_FLOATS (CR * CC + CC * CR + 2 * CC + CC + CR + CC)
#define SMEM_BYTES  (SMEM_FLOATS * 4)

// ---------------------------------------------------------------------------
// Kernel 1: f0[b,c] = mean over H*W of x[b,c,:,:]  (DRAM roofline, ~71 us)
// ---------------------------------------------------------------------------
__global__ __launch_bounds__(256) void row_mean_kernel(const float* __restrict__ x) {
    const int row = blockIdx.x;                  // b*C + c
    const float4* __restrict__ p =
        reinterpret_cast<const float4*>(x) + (size_t)row * (HW / 4);
    const int t = threadIdx.x;

    float s = 0.0f;
#pragma unroll
    for (int k = 0; k < 16; k++) {
        float4 v = __ldcs(p + k * 256 + t);
        s += (v.x + v.y) + (v.z + v.w);
    }
#pragma unroll
    for (int o = 16; o > 0; o >>= 1)
        s += __shfl_xor_sync(0xffffffffu, s, o);

    __shared__ float part[8];
    if ((t & 31) == 0) part[t >> 5] = s;
    __syncthreads();

    if (t < 8) {
        float v = part[t];
#pragma unroll
        for (int o = 4; o > 0; o >>= 1)
            v += __shfl_xor_sync(0x000000ffu, v, o);
        if (t == 0) g_f0[row] = v * (1.0f / HW);
    }
}

// ---------------------------------------------------------------------------
// Kernel 2: fused SE-MLP, one block per batch element.
// Step 0: burst-load ALL weights into smem (one parallel DRAM round-trip).
// Steps 1-3 run entirely from smem.
// ---------------------------------------------------------------------------
__global__ __launch_bounds__(256) void fused_mlp_kernel(const float* __restrict__ W1,
                                                        const float* __restrict__ W2,
                                                        const float* __restrict__ W3,
                                                        const float* __restrict__ b3,
                                                        float* __restrict__ out) {
    extern __shared__ float sw[];
    float* W1s = sw;                       // CR*CC = 16384
    float* W2s = W1s + CR * CC;            // CC*CR = 16384
    float* W3s = W2s + CC * CR;            // 2*CC  = 512
    float* f0s = W3s + 2 * CC;             // 256
    float* hs  = f0s + CC;                 // 64
    float* ps  = hs + CR;                  // 256

    const int b    = blockIdx.x;
    const int t    = threadIdx.x;
    const int warp = t >> 5;
    const int lane = t & 31;

    // ---- step 0: fully parallel weight burst (all loads independent) ------
    {
        const float4* __restrict__ s1 = reinterpret_cast<const float4*>(W1);
        const float4* __restrict__ s2 = reinterpret_cast<const float4*>(W2);
        const float4* __restrict__ s3 = reinterpret_cast<const float4*>(W3);
        float4* d1 = reinterpret_cast<float4*>(W1s);
        float4* d2 = reinterpret_cast<float4*>(W2s);
        float4* d3 = reinterpret_cast<float4*>(W3s);
#pragma unroll
        for (int k = 0; k < 16; k++) d1[k * 256 + t] = __ldg(s1 + k * 256 + t);
#pragma unroll
        for (int k = 0; k < 16; k++) d2[k * 256 + t] = __ldg(s2 + k * 256 + t);
        if (t < 128) d3[t] = __ldg(s3 + t);
        if (t < CC)  f0s[t] = g_f0[b * CC + t];
    }
    __syncthreads();

    // ---- stage 1: h[j] = relu(f0 . W1[j,:]), 8 outputs/warp, ILP8 --------
    {
        float acc[8];
#pragma unroll
        for (int u = 0; u < 8; u++) acc[u] = 0.0f;
#pragma unroll
        for (int k = 0; k < 8; k++) {
            const int c = k * 32 + lane;
            const float f = f0s[c];
#pragma unroll
            for (int u = 0; u < 8; u++)
                acc[u] = fmaf(f, W1s[(warp * 8 + u) * CC + c], acc[u]);
        }
#pragma unroll
        for (int o = 16; o > 0; o >>= 1)
#pragma unroll
            for (int u = 0; u < 8; u++)
                acc[u] += __shfl_xor_sync(0xffffffffu, acc[u], o);
        if (lane == 0) {
#pragma unroll
            for (int u = 0; u < 8; u++)
                hs[warp * 8 + u] = fmaxf(acc[u], 0.0f);
        }
    }
    __syncthreads();

    // ---- stage 2: p[c] = sigmoid(h . W2[c,:]) * f0[c], 32 outputs/warp ----
    {
        const float hv0 = hs[lane];
        const float hv1 = hs[lane + 32];
#pragma unroll
        for (int g = 0; g < 4; g++) {
            float acc[8];
#pragma unroll
            for (int u = 0; u < 8; u++) {
                const int c = warp * 32 + g * 8 + u;
                const float* __restrict__ w = W2s + c * CR;
                acc[u] = fmaf(hv0, w[lane], hv1 * w[lane + 32]);
            }
#pragma unroll
            for (int o = 16; o > 0; o >>= 1)
#pragma unroll
                for (int u = 0; u < 8; u++)
                    acc[u] += __shfl_xor_sync(0xffffffffu, acc[u], o);
            if (lane == 0) {
#pragma unroll
                for (int u = 0; u < 8; u++) {
                    const int c = warp * 32 + g * 8 + u;
                    const float gsig = 1.0f / (1.0f + __expf(-acc[u]));
                    ps[c] = gsig * f0s[c];
                }
            }
        }
    }
    __syncthreads();

    // ---- stage 3: out[b,o] = p . W3[o,:] + b3[o] --------------------------
    if (warp < 2) {
        const int o = warp;
        const float* __restrict__ w = W3s + o * CC;
        float acc = 0.0f;
#pragma unroll
        for (int k = 0; k < 8; k++) {
            const int c = k * 32 + lane;
            acc = fmaf(ps[c], w[c], acc);
        }
#pragma unroll
        for (int s = 16; s > 0; s >>= 1)
            acc += __shfl_xor_sync(0xffffffffu, acc, s);
        if (lane == 0) out[b * 2 + o] = acc + b3[o];
    }
}

// ---------------------------------------------------------------------------
extern "C" void kernel_launch(void* const* d_in, const int* in_sizes, int n_in,
                              void* d_out, int out_size) {
    const float* x  = (const float*)d_in[0];  // (32,256,128,128)
    const float* W1 = (const float*)d_in[1];  // (64,256)
    const float* W2 = (const float*)d_in[2];  // (256,64)
    const float* W3 = (const float*)d_in[3];  // (2,256)
    const float* b3 = (const float*)d_in[4];  // (2,)
    float* out = (float*)d_out;               // (32,2)

    cudaFuncSetAttribute(fused_mlp_kernel,
                         cudaFuncAttributeMaxDynamicSharedMemorySize, SMEM_BYTES);

    row_mean_kernel<<<BB * CC, 256>>>(x);
    fused_mlp_kernel<<<BB, 256, SMEM_BYTES>>>(W1, W2, W3, b3, out);
}

// round 12
// speedup vs baseline: 1.0766x; 1.0071x over previous
#include <cuda_runtime.h>
#include <math.h>

#define BB 32
#define CC 256
#define CR 64
#define HW 16384   // 128*128

// allocation-free scratch: pooled means
__device__ float g_f0[BB * CC];

// dynamic smem layout (floats):
//   W1s [CR*CC] | W2s [CC*CR] | W3s [2*CC] | f0s [CC] | hs [CR] | ps [CC]
#define SMEM_FLOATS (CR * CC + CC * CR + 2 * CC + CC + CR + CC)
#define SMEM_BYTES  (SMEM_FLOATS * 4)

// ---------------------------------------------------------------------------
// Kernel 1: f0[b,c] = mean over H*W of x[b,c,:,:]  (DRAM roofline)
// Signals dependent launch (PDL) after its g_f0 write is fenced.
// ---------------------------------------------------------------------------
__global__ __launch_bounds__(256) void row_mean_kernel(const float* __restrict__ x) {
    const int row = blockIdx.x;                  // b*C + c
    const float4* __restrict__ p =
        reinterpret_cast<const float4*>(x) + (size_t)row * (HW / 4);
    const int t = threadIdx.x;

    float s = 0.0f;
#pragma unroll
    for (int k = 0; k < 16; k++) {
        float4 v = __ldcs(p + k * 256 + t);
        s += (v.x + v.y) + (v.z + v.w);
    }
#pragma unroll
    for (int o = 16; o > 0; o >>= 1)
        s += __shfl_xor_sync(0xffffffffu, s, o);

    __shared__ float part[8];
    if ((t & 31) == 0) part[t >> 5] = s;
    __syncthreads();

    if (t < 8) {
        float v = part[t];
#pragma unroll
        for (int o = 4; o > 0; o >>= 1)
            v += __shfl_xor_sync(0x000000ffu, v, o);
        if (t == 0) {
            g_f0[row] = v * (1.0f / HW);
            __threadfence();
        }
    }
    __syncthreads();
    // allow dependent grid to pass its griddepcontrol.wait once ALL blocks
    // have executed this (i.e., all g_f0 writes are fenced & visible)
    if (t == 0)
        asm volatile("griddepcontrol.launch_dependents;");
}

// ---------------------------------------------------------------------------
// Kernel 2: fused SE-MLP, one block per batch element. Launched with PDL:
// starts during row_mean, burst-loads all weights into smem (independent of
// g_f0), then griddepcontrol.wait, then computes entirely from smem.
// ---------------------------------------------------------------------------
__global__ __launch_bounds__(256) void fused_mlp_kernel(const float* __restrict__ W1,
                                                        const float* __restrict__ W2,
                                                        const float* __restrict__ W3,
                                                        const float* __restrict__ b3,
                                                        float* __restrict__ out) {
    extern __shared__ float sw[];
    float* W1s = sw;                       // CR*CC = 16384
    float* W2s = W1s + CR * CC;            // CC*CR = 16384
    float* W3s = W2s + CC * CR;            // 2*CC  = 512
    float* f0s = W3s + 2 * CC;             // 256
    float* hs  = f0s + CC;                 // 64
    float* ps  = hs + CR;                  // 256

    const int b    = blockIdx.x;
    const int t    = threadIdx.x;
    const int warp = t >> 5;
    const int lane = t & 31;

    // ---- step 0: weight burst (overlaps with row_mean under PDL) ----------
    {
        const float4* __restrict__ s1 = reinterpret_cast<const float4*>(W1);
        const float4* __restrict__ s2 = reinterpret_cast<const float4*>(W2);
        const float4* __restrict__ s3 = reinterpret_cast<const float4*>(W3);
        float4* d1 = reinterpret_cast<float4*>(W1s);
        float4* d2 = reinterpret_cast<float4*>(W2s);
        float4* d3 = reinterpret_cast<float4*>(W3s);
#pragma unroll
        for (int k = 0; k < 16; k++) d1[k * 256 + t] = __ldg(s1 + k * 256 + t);
#pragma unroll
        for (int k = 0; k < 16; k++) d2[k * 256 + t] = __ldg(s2 + k * 256 + t);
        if (t < 128) d3[t] = __ldg(s3 + t);
    }

    // wait for primary grid's g_f0 to be complete & visible
    asm volatile("griddepcontrol.wait;" ::: "memory");

    if (t < CC) f0s[t] = g_f0[b * CC + t];
    __syncthreads();

    // ---- stage 1: h[j] = relu(f0 . W1[j,:]), 8 outputs/warp, ILP8 --------
    {
        float acc[8];
#pragma unroll
        for (int u = 0; u < 8; u++) acc[u] = 0.0f;
#pragma unroll
        for (int k = 0; k < 8; k++) {
            const int c = k * 32 + lane;
            const float f = f0s[c];
#pragma unroll
            for (int u = 0; u < 8; u++)
                acc[u] = fmaf(f, W1s[(warp * 8 + u) * CC + c], acc[u]);
        }
#pragma unroll
        for (int o = 16; o > 0; o >>= 1)
#pragma unroll
            for (int u = 0; u < 8; u++)
                acc[u] += __shfl_xor_sync(0xffffffffu, acc[u], o);
        if (lane == 0) {
#pragma unroll
            for (int u = 0; u < 8; u++)
                hs[warp * 8 + u] = fmaxf(acc[u], 0.0f);
        }
    }
    __syncthreads();

    // ---- stage 2: p[c] = sigmoid(h . W2[c,:]) * f0[c], 32 outputs/warp ----
    {
        const float hv0 = hs[lane];
        const float hv1 = hs[lane + 32];
#pragma unroll
        for (int g = 0; g < 4; g++) {
            float acc[8];
#pragma unroll
            for (int u = 0; u < 8; u++) {
                const int c = warp * 32 + g * 8 + u;
                const float* __restrict__ w = W2s + c * CR;
                acc[u] = fmaf(hv0, w[lane], hv1 * w[lane + 32]);
            }
#pragma unroll
            for (int o = 16; o > 0; o >>= 1)
#pragma unroll
                for (int u = 0; u < 8; u++)
                    acc[u] += __shfl_xor_sync(0xffffffffu, acc[u], o);
            if (lane == 0) {
#pragma unroll
                for (int u = 0; u < 8; u++) {
                    const int c = warp * 32 + g * 8 + u;
                    const float gsig = 1.0f / (1.0f + __expf(-acc[u]));
                    ps[c] = gsig * f0s[c];
                }
            }
        }
    }
    __syncthreads();

    // ---- stage 3: out[b,o] = p . W3[o,:] + b3[o] --------------------------
    if (warp < 2) {
        const int o = warp;
        const float* __restrict__ w = W3s + o * CC;
        float acc = 0.0f;
#pragma unroll
        for (int k = 0; k < 8; k++) {
            const int c = k * 32 + lane;
            acc = fmaf(ps[c], w[c], acc);
        }
#pragma unroll
        for (int s = 16; s > 0; s >>= 1)
            acc += __shfl_xor_sync(0xffffffffu, acc, s);
        if (lane == 0) out[b * 2 + o] = acc + b3[o];
    }
}

// ---------------------------------------------------------------------------
extern "C" void kernel_launch(void* const* d_in, const int* in_sizes, int n_in,
                              void* d_out, int out_size) {
    const float* x  = (const float*)d_in[0];  // (32,256,128,128)
    const float* W1 = (const float*)d_in[1];  // (64,256)
    const float* W2 = (const float*)d_in[2];  // (256,64)
    const float* W3 = (const float*)d_in[3];  // (2,256)
    const float* b3 = (const float*)d_in[4];  // (2,)
    float* out = (float*)d_out;               // (32,2)

    cudaFuncSetAttribute(fused_mlp_kernel,
                         cudaFuncAttributeMaxDynamicSharedMemorySize, SMEM_BYTES);

    row_mean_kernel<<<BB * CC, 256>>>(x);

    // dependent launch with programmatic overlap (PDL)
    cudaLaunchConfig_t cfg = {};
    cfg.gridDim          = dim3(BB);
    cfg.blockDim         = dim3(256);
    cfg.dynamicSmemBytes = SMEM_BYTES;
    cfg.stream           = 0;
    cudaLaunchAttribute attrs[1];
    attrs[0].id = cudaLaunchAttributeProgrammaticStreamSerialization;
    attrs[0].val.programmaticStreamSerializationAllowed = 1;
    cfg.attrs    = attrs;
    cfg.numAttrs = 1;
    cudaLaunchKernelEx(&cfg, fused_mlp_kernel, W1, W2, W3, b3, out);
}

// round 14
// speedup vs baseline: 1.1028x; 1.0244x over previous
#include <cuda_runtime.h>
#include <cstdint>
#include <math.h>

#define BB 32
#define CC 256
#define CR 64
#define HW 16384   // 128*128

// allocation-free scratch: pooled means
__device__ float g_f0[BB * CC];

// dynamic smem layout (floats):
//   W1s [CR*CC] | W2s [CC*CR] | W3s [2*CC] | f0s [CC] | hs [CR] | ps [CC]
#define SMEM_FLOATS (CR * CC + CC * CR + 2 * CC + CC + CR + CC)
#define SMEM_BYTES  (SMEM_FLOATS * 4)

// 16-byte async copy GMEM -> SMEM, no register involvement (LDGSTS)
__device__ __forceinline__ void cp16(unsigned int dst_smem, const void* src) {
    asm volatile("cp.async.cg.shared.global [%0], [%1], 16;"
                 :: "r"(dst_smem), "l"(src) : "memory");
}

// ---------------------------------------------------------------------------
// Kernel 1: f0[b,c] = mean over H*W of x[b,c,:,:]  (DRAM roofline)
// ---------------------------------------------------------------------------
__global__ __launch_bounds__(256) void row_mean_kernel(const float* __restrict__ x) {
    const int row = blockIdx.x;                  // b*C + c
    const float4* __restrict__ p =
        reinterpret_cast<const float4*>(x) + (size_t)row * (HW / 4);
    const int t = threadIdx.x;

    float s = 0.0f;
#pragma unroll
    for (int k = 0; k < 16; k++) {
        float4 v = __ldcs(p + k * 256 + t);
        s += (v.x + v.y) + (v.z + v.w);
    }
#pragma unroll
    for (int o = 16; o > 0; o >>= 1)
        s += __shfl_xor_sync(0xffffffffu, s, o);

    __shared__ float part[8];
    if ((t & 31) == 0) part[t >> 5] = s;
    __syncthreads();

    if (t < 8) {
        float v = part[t];
#pragma unroll
        for (int o = 4; o > 0; o >>= 1)
            v += __shfl_xor_sync(0x000000ffu, v, o);
        if (t == 0) {
            g_f0[row] = v * (1.0f / HW);
            __threadfence();
        }
    }
    __syncthreads();
    if (t == 0)
        asm volatile("griddepcontrol.launch_dependents;");
}

// ---------------------------------------------------------------------------
// Kernel 2: fused SE-MLP, one block per batch element (PDL dependent).
// Weight burst uses cp.async (LDGSTS): no register cap -> all 132 KB in one
// DRAM round-trip. Then compute entirely from smem.
// ---------------------------------------------------------------------------
__global__ __launch_bounds__(256) void fused_mlp_kernel(const float* __restrict__ W1,
                                                        const float* __restrict__ W2,
                                                        const float* __restrict__ W3,
                                                        const float* __restrict__ b3,
                                                        float* __restrict__ out) {
    extern __shared__ float sw[];
    float* W1s = sw;                       // CR*CC = 16384
    float* W2s = W1s + CR * CC;            // CC*CR = 16384
    float* W3s = W2s + CC * CR;            // 2*CC  = 512
    float* f0s = W3s + 2 * CC;             // 256
    float* hs  = f0s + CC;                 // 64
    float* ps  = hs + CR;                  // 256

    const int b    = blockIdx.x;
    const int t    = threadIdx.x;
    const int warp = t >> 5;
    const int lane = t & 31;

    // ---- step 0: async weight burst (all LDGSTS independent, in-flight) ---
    {
        const unsigned int w1d = (unsigned int)__cvta_generic_to_shared(W1s);
        const unsigned int w2d = (unsigned int)__cvta_generic_to_shared(W2s);
        const unsigned int w3d = (unsigned int)__cvta_generic_to_shared(W3s);
        const float4* __restrict__ s1 = reinterpret_cast<const float4*>(W1);
        const float4* __restrict__ s2 = reinterpret_cast<const float4*>(W2);
        const float4* __restrict__ s3 = reinterpret_cast<const float4*>(W3);
#pragma unroll
        for (int k = 0; k < 16; k++)
            cp16(w1d + (k * 256 + t) * 16, s1 + k * 256 + t);
#pragma unroll
        for (int k = 0; k < 16; k++)
            cp16(w2d + (k * 256 + t) * 16, s2 + k * 256 + t);
        if (t < 128)
            cp16(w3d + t * 16, s3 + t);
        asm volatile("cp.async.commit_group;" ::: "memory");
    }

    // wait for primary grid's g_f0 writes to be complete & visible
    asm volatile("griddepcontrol.wait;" ::: "memory");

    if (t < CC) f0s[t] = g_f0[b * CC + t];

    asm volatile("cp.async.wait_group 0;" ::: "memory");
    __syncthreads();

    // ---- stage 1: h[j] = relu(f0 . W1[j,:]), 8 outputs/warp, ILP8 --------
    {
        float acc[8];
#pragma unroll
        for (int u = 0; u < 8; u++) acc[u] = 0.0f;
#pragma unroll
        for (int k = 0; k < 8; k++) {
            const int c = k * 32 + lane;
            const float f = f0s[c];
#pragma unroll
            for (int u = 0; u < 8; u++)
                acc[u] = fmaf(f, W1s[(warp * 8 + u) * CC + c], acc[u]);
        }
#pragma unroll
        for (int o = 16; o > 0; o >>= 1)
#pragma unroll
            for (int u = 0; u < 8; u++)
                acc[u] += __shfl_xor_sync(0xffffffffu, acc[u], o);
        if (lane == 0) {
#pragma unroll
            for (int u = 0; u < 8; u++)
                hs[warp * 8 + u] = fmaxf(acc[u], 0.0f);
        }
    }
    __syncthreads();

    // ---- stage 2: p[c] = sigmoid(h . W2[c,:]) * f0[c], 32 outputs/warp ----
    {
        const float hv0 = hs[lane];
        const float hv1 = hs[lane + 32];
#pragma unroll
        for (int g = 0; g < 4; g++) {
            float acc[8];
#pragma unroll
            for (int u = 0; u < 8; u++) {
                const int c = warp * 32 + g * 8 + u;
                const float* __restrict__ w = W2s + c * CR;
                acc[u] = fmaf(hv0, w[lane], hv1 * w[lane + 32]);
            }
#pragma unroll
            for (int o = 16; o > 0; o >>= 1)
#pragma unroll
                for (int u = 0; u < 8; u++)
                    acc[u] += __shfl_xor_sync(0xffffffffu, acc[u], o);
            if (lane == 0) {
#pragma unroll
                for (int u = 0; u < 8; u++) {
                    const int c = warp * 32 + g * 8 + u;
                    const float gsig = 1.0f / (1.0f + __expf(-acc[u]));
                    ps[c] = gsig * f0s[c];
                }
            }
        }
    }
    __syncthreads();

    // ---- stage 3: out[b,o] = p . W3[o,:] + b3[o] --------------------------
    if (warp < 2) {
        const int o = warp;
        const float* __restrict__ w = W3s + o * CC;
        float acc = 0.0f;
#pragma unroll
        for (int k = 0; k < 8; k++) {
            const int c = k * 32 + lane;
            acc = fmaf(ps[c], w[c], acc);
        }
#pragma unroll
        for (int s = 16; s > 0; s >>= 1)
            acc += __shfl_xor_sync(0xffffffffu, acc, s);
        if (lane == 0) out[b * 2 + o] = acc + b3[o];
    }
}

// ---------------------------------------------------------------------------
extern "C" void kernel_launch(void* const* d_in, const int* in_sizes, int n_in,
                              void* d_out, int out_size) {
    const float* x  = (const float*)d_in[0];  // (32,256,128,128)
    const float* W1 = (const float*)d_in[1];  // (64,256)
    const float* W2 = (const float*)d_in[2];  // (256,64)
    const float* W3 = (const float*)d_in[3];  // (2,256)
    const float* b3 = (const float*)d_in[4];  // (2,)
    float* out = (float*)d_out;               // (32,2)

    cudaFuncSetAttribute(fused_mlp_kernel,
                         cudaFuncAttributeMaxDynamicSharedMemorySize, SMEM_BYTES);

    row_mean_kernel<<<BB * CC, 256>>>(x);

    cudaLaunchConfig_t cfg = {};
    cfg.gridDim          = dim3(BB);
    cfg.blockDim         = dim3(256);
    cfg.dynamicSmemBytes = SMEM_BYTES;
    cfg.stream           = 0;
    cudaLaunchAttribute attrs[1];
    attrs[0].id = cudaLaunchAttributeProgrammaticStreamSerialization;
    attrs[0].val.programmaticStreamSerializationAllowed = 1;
    cfg.attrs    = attrs;
    cfg.numAttrs = 1;
    cudaLaunchKernelEx(&cfg, fused_mlp_kernel, W1, W2, W3, b3, out);
}